// round 1
// baseline (speedup 1.0000x reference)
#include <cuda_runtime.h>
#include <math.h>

#define B_ 4
#define S_ 1024
#define D_ 512
#define H_ 8
#define E_ 64
#define BS_ (B_*S_)

// Scratch (device globals — no runtime allocation allowed)
__device__ float g_Q[H_*BS_*E_];     // [H][B*S][E]  8 MB
__device__ float g_K[H_*BS_*E_];     // 8 MB
__device__ float g_V[BS_*E_];        // [B*S][E]     1 MB
__device__ float g_M[BS_*E_];        // mean-over-heads accumulator [B][S][E]
__device__ float g_G[B_*128*D_];     // final-GEMM output [B][128][512]

// ---------------------------------------------------------------------------
__global__ void zero_m_kernel() {
    int i = blockIdx.x * blockDim.x + threadIdx.x;
    int stride = gridDim.x * blockDim.x;
    for (; i < BS_*E_; i += stride) g_M[i] = 0.f;
}

// ---------------------------------------------------------------------------
// Batched projections: p in [0,8)->Q head p, [8,16)->K head p-8, 16->V.
// out[64x64 tile] = A[BS x D] @ W[D x 64] + bias
__global__ void proj_kernel(const float* __restrict__ q, const float* __restrict__ k,
                            const float* __restrict__ v,
                            const float* __restrict__ Wq, const float* __restrict__ bq,
                            const float* __restrict__ Wk, const float* __restrict__ bk,
                            const float* __restrict__ Wv, const float* __restrict__ bv) {
    const int p = blockIdx.y;
    const float* A; const float* W; const float* bias; float* out;
    if (p < 8)       { A = q; W = Wq + (size_t)p*D_*E_;     bias = bq + p*E_;     out = g_Q + (size_t)p*BS_*E_; }
    else if (p < 16) { A = k; W = Wk + (size_t)(p-8)*D_*E_; bias = bk + (p-8)*E_; out = g_K + (size_t)(p-8)*BS_*E_; }
    else             { A = v; W = Wv;                        bias = bv;            out = g_V; }

    __shared__ float As[64][32];
    __shared__ float Ws[32][68];
    const int m0  = blockIdx.x * 64;
    const int tid = threadIdx.x;
    const int tx  = tid & 15, ty = tid >> 4;
    float acc[4][4] = {};

    for (int k0 = 0; k0 < D_; k0 += 32) {
        #pragma unroll
        for (int t = 0; t < 2; t++) {
            int f = tid + t*256;
            int r = f >> 3, c = (f & 7) * 4;
            *(float4*)&As[r][c] = *(const float4*)&A[(size_t)(m0 + r)*D_ + k0 + c];
        }
        #pragma unroll
        for (int t = 0; t < 2; t++) {
            int f = tid + t*256;
            int r = f >> 4, c = (f & 15) * 4;
            *(float4*)&Ws[r][c] = *(const float4*)&W[(size_t)(k0 + r)*E_ + c];
        }
        __syncthreads();
        #pragma unroll
        for (int kk = 0; kk < 32; kk++) {
            float a[4], b[4];
            #pragma unroll
            for (int i = 0; i < 4; i++) a[i] = As[ty*4+i][kk];
            #pragma unroll
            for (int j = 0; j < 4; j++) b[j] = Ws[kk][tx*4+j];
            #pragma unroll
            for (int i = 0; i < 4; i++)
                #pragma unroll
                for (int j = 0; j < 4; j++)
                    acc[i][j] += a[i]*b[j];
        }
        __syncthreads();
    }
    #pragma unroll
    for (int i = 0; i < 4; i++)
        #pragma unroll
        for (int j = 0; j < 4; j++)
            out[(size_t)(m0 + ty*4+i)*E_ + tx*4+j] = acc[i][j] + bias[tx*4+j];
}

// ---------------------------------------------------------------------------
// Flash-style causal attention, fp32, per (qtile, b, h). 64x64 tiles, E=64.
// Each head atomically adds o / (l * H) into g_M (mean over heads).
__global__ void attn_kernel() {
    const int qt = blockIdx.x, b = blockIdx.y, h = blockIdx.z;
    extern __shared__ float sm[];
    float* Qs   = sm;              // 64*65
    float* Ks   = Qs + 64*65;
    float* Vs   = Ks + 64*65;
    float* Ss   = Vs + 64*65;
    float* m_sh = Ss + 64*65;      // 64
    float* l_sh = m_sh + 64;       // 64
    float* c_sh = l_sh + 64;       // 64

    const int tid = threadIdx.x;
    const int tx = tid & 15, ty = tid >> 4;
    const float* Qp = g_Q + (((size_t)h*B_ + b)*S_ + (size_t)qt*64)*E_;
    const float* Kp = g_K + ((size_t)h*B_ + b)*S_*E_;
    const float* Vp = g_V + (size_t)b*S_*E_;

    #pragma unroll
    for (int t = 0; t < 16; t++) {
        int f = tid + t*256;
        int r = f >> 6, c = f & 63;
        Qs[r*65 + c] = Qp[r*64 + c];
    }
    if (tid < 64) { m_sh[tid] = -1e30f; l_sh[tid] = 0.f; }

    float o[4][4] = {};
    for (int j = 0; j <= qt; j++) {
        __syncthreads();   // previous PV reads done; init visible on first iter
        #pragma unroll
        for (int t = 0; t < 16; t++) {
            int f = tid + t*256;
            int r = f >> 6, c = f & 63;
            Ks[r*65 + c] = Kp[(size_t)(j*64 + r)*64 + c];
            Vs[r*65 + c] = Vp[(size_t)(j*64 + r)*64 + c];
        }
        __syncthreads();

        float s[4][4] = {};
        #pragma unroll
        for (int kk = 0; kk < 64; kk++) {
            float a[4], bb[4];
            #pragma unroll
            for (int i = 0; i < 4; i++)  a[i]  = Qs[(ty*4+i)*65 + kk];
            #pragma unroll
            for (int jj = 0; jj < 4; jj++) bb[jj] = Ks[(tx*4+jj)*65 + kk];
            #pragma unroll
            for (int i = 0; i < 4; i++)
                #pragma unroll
                for (int jj = 0; jj < 4; jj++)
                    s[i][jj] += a[i]*bb[jj];
        }
        const bool diag = (j == qt);
        #pragma unroll
        for (int i = 0; i < 4; i++)
            #pragma unroll
            for (int jj = 0; jj < 4; jj++) {
                float val = s[i][jj] * 0.125f;           // 1/sqrt(E)
                if (diag && (tx*4+jj) > (ty*4+i)) val = -1e30f;
                Ss[(ty*4+i)*65 + tx*4+jj] = val;
            }
        __syncthreads();

        if (tid < 64) {                                   // online softmax, one row each
            float mold = m_sh[tid];
            float mx = mold;
            for (int c = 0; c < 64; c++) mx = fmaxf(mx, Ss[tid*65 + c]);
            float corr = __expf(mold - mx);
            float sum = 0.f;
            for (int c = 0; c < 64; c++) {
                float pv = __expf(Ss[tid*65 + c] - mx);
                Ss[tid*65 + c] = pv;
                sum += pv;
            }
            l_sh[tid] = l_sh[tid]*corr + sum;
            m_sh[tid] = mx;
            c_sh[tid] = corr;
        }
        __syncthreads();

        #pragma unroll
        for (int i = 0; i < 4; i++) {
            float cf = c_sh[ty*4+i];
            #pragma unroll
            for (int jj = 0; jj < 4; jj++) o[i][jj] *= cf;
        }
        #pragma unroll
        for (int kk = 0; kk < 64; kk++) {
            float pp[4], vv[4];
            #pragma unroll
            for (int i = 0; i < 4; i++)   pp[i]  = Ss[(ty*4+i)*65 + kk];
            #pragma unroll
            for (int jj = 0; jj < 4; jj++) vv[jj] = Vs[kk*65 + tx*4+jj];
            #pragma unroll
            for (int i = 0; i < 4; i++)
                #pragma unroll
                for (int jj = 0; jj < 4; jj++)
                    o[i][jj] += pp[i]*vv[jj];
        }
    }
    __syncthreads();
    #pragma unroll
    for (int i = 0; i < 4; i++) {
        int r = ty*4 + i;
        float inv = 1.f / (l_sh[r] * (float)H_);
        #pragma unroll
        for (int jj = 0; jj < 4; jj++)
            atomicAdd(&g_M[((size_t)b*S_ + qt*64 + r)*E_ + tx*4 + jj], o[i][jj]*inv);
    }
}

// ---------------------------------------------------------------------------
// Final linear. Key identity: the broadcast/transpose/reshape scramble is the
// IDENTITY on g_M flattened as [B*128, 512]. So G = g_M[512,512] @ Wf[512,512].
__global__ void gemm_g_kernel(const float* __restrict__ Wf) {
    __shared__ float As[64][32];
    __shared__ float Ws[32][68];
    const int m0 = blockIdx.x * 64, n0 = blockIdx.y * 64;
    const int tid = threadIdx.x;
    const int tx = tid & 15, ty = tid >> 4;
    float acc[4][4] = {};
    for (int k0 = 0; k0 < 512; k0 += 32) {
        #pragma unroll
        for (int t = 0; t < 2; t++) {
            int f = tid + t*256;
            int r = f >> 3, c = (f & 7) * 4;
            *(float4*)&As[r][c] = *(const float4*)&g_M[(size_t)(m0 + r)*512 + k0 + c];
        }
        #pragma unroll
        for (int t = 0; t < 2; t++) {
            int f = tid + t*256;
            int r = f >> 4, c = (f & 15) * 4;
            *(float4*)&Ws[r][c] = *(const float4*)&Wf[(size_t)(k0 + r)*512 + n0 + c];
        }
        __syncthreads();
        #pragma unroll
        for (int kk = 0; kk < 32; kk++) {
            float a[4], b[4];
            #pragma unroll
            for (int i = 0; i < 4; i++) a[i] = As[ty*4+i][kk];
            #pragma unroll
            for (int j = 0; j < 4; j++) b[j] = Ws[kk][tx*4+j];
            #pragma unroll
            for (int i = 0; i < 4; i++)
                #pragma unroll
                for (int j = 0; j < 4; j++)
                    acc[i][j] += a[i]*b[j];
        }
        __syncthreads();
    }
    #pragma unroll
    for (int i = 0; i < 4; i++)
        #pragma unroll
        for (int j = 0; j < 4; j++)
            g_G[(size_t)(m0 + ty*4+i)*512 + n0 + tx*4+j] = acc[i][j];
}

// ---------------------------------------------------------------------------
// x = G[b, s%128, :] + bf + query[b,s,:]; torch-style LN: std with ddof=1, (std+eps)
__global__ void ln_kernel(const float* __restrict__ query, const float* __restrict__ bf,
                          const float* __restrict__ lnw, const float* __restrict__ lnb,
                          float* __restrict__ out) {
    const int row  = blockIdx.x;            // b*1024 + s
    const int bb   = row >> 10;
    const int r128 = row & 127;             // (b*1024+s)%128 == s%128
    const float* g    = g_G + ((size_t)bb*128 + r128)*D_;
    const float* qrow = query + (size_t)row*D_;
    const int tid = threadIdx.x;            // 128 threads, 4 elems each
    float x[4];
    float sum = 0.f;
    #pragma unroll
    for (int t = 0; t < 4; t++) {
        int c = tid + t*128;
        x[t] = g[c] + bf[c] + qrow[c];
        sum += x[t];
    }
    __shared__ float red[4];
    __shared__ float red2[4];
    #pragma unroll
    for (int off = 16; off; off >>= 1) sum += __shfl_xor_sync(0xffffffffu, sum, off);
    if ((tid & 31) == 0) red[tid >> 5] = sum;
    __syncthreads();
    float mean = (red[0]+red[1]+red[2]+red[3]) * (1.f/512.f);

    float sq = 0.f;
    #pragma unroll
    for (int t = 0; t < 4; t++) { float d = x[t] - mean; sq += d*d; }
    #pragma unroll
    for (int off = 16; off; off >>= 1) sq += __shfl_xor_sync(0xffffffffu, sq, off);
    if ((tid & 31) == 0) red2[tid >> 5] = sq;
    __syncthreads();
    float var_num = red2[0]+red2[1]+red2[2]+red2[3];
    float stdv = sqrtf(var_num * (1.f/511.f));
    float inv  = 1.f / (stdv + 1e-6f);
    #pragma unroll
    for (int t = 0; t < 4; t++) {
        int c = tid + t*128;
        out[(size_t)row*D_ + c] = lnw[c]*(x[t]-mean)*inv + lnb[c];
    }
}

// ---------------------------------------------------------------------------
extern "C" void kernel_launch(void* const* d_in, const int* in_sizes, int n_in,
                              void* d_out, int out_size) {
    const float* query = (const float*)d_in[0];
    const float* key   = (const float*)d_in[1];
    const float* value = (const float*)d_in[2];
    // d_in[3] = mask (tril, handled analytically)
    const float* Wq = (const float*)d_in[4];
    const float* bq = (const float*)d_in[5];
    const float* Wk = (const float*)d_in[6];
    const float* bk = (const float*)d_in[7];
    const float* Wv = (const float*)d_in[8];
    const float* bv = (const float*)d_in[9];
    const float* Wf = (const float*)d_in[10];
    const float* bf = (const float*)d_in[11];
    const float* lnw = (const float*)d_in[12];
    const float* lnb = (const float*)d_in[13];
    float* out = (float*)d_out;

    const size_t attn_smem = (size_t)(4*64*65 + 3*64) * sizeof(float);  // 67328 B
    cudaFuncSetAttribute(attn_kernel, cudaFuncAttributeMaxDynamicSharedMemorySize,
                         (int)attn_smem);

    zero_m_kernel<<<64, 256>>>();
    proj_kernel<<<dim3(BS_/64, 17), 256>>>(query, key, value, Wq, bq, Wk, bk, Wv, bv);
    attn_kernel<<<dim3(S_/64, B_, H_), 256, attn_smem>>>();
    gemm_g_kernel<<<dim3(8, 8), 256>>>(Wf);
    ln_kernel<<<BS_, 128>>>(query, bf, lnw, lnb, out);
}

// round 5
// speedup vs baseline: 1.0822x; 1.0822x over previous
#include <cuda_runtime.h>
#include <math.h>
#include <stdint.h>

#define B_ 4
#define S_ 1024
#define D_ 512
#define H_ 8
#define E_ 64
#define BS_ (B_*S_)

// Scratch (device globals — no runtime allocation allowed)
__device__ float g_Q[H_*BS_*E_];     // [H][B*S][E]
__device__ float g_K[H_*BS_*E_];
__device__ float g_V[BS_*E_];
__device__ float g_M[BS_*E_];        // mean-over-heads accumulator
__device__ float g_G[B_*128*D_];     // final-GEMM output [512][512]

// ---------------------------------------------------------------------------
__device__ __forceinline__ uint32_t f2tf32(float x) {
    uint32_t r;
    asm("cvt.rna.tf32.f32 %0, %1;" : "=r"(r) : "f"(x));
    return r;
}
__device__ __forceinline__ void split_tf32(float x, uint32_t& hi, uint32_t& lo) {
    hi = f2tf32(x);
    lo = f2tf32(x - __uint_as_float(hi));
}

// D += A(16x8,row) * B(8x8,col)   tf32, fp32 accum
__device__ __forceinline__ void mma_tf32(float c[4],
                                         uint32_t a0, uint32_t a1, uint32_t a2, uint32_t a3,
                                         uint32_t b0, uint32_t b1) {
    asm volatile(
        "mma.sync.aligned.m16n8k8.row.col.f32.tf32.tf32.f32 "
        "{%0,%1,%2,%3}, {%4,%5,%6,%7}, {%8,%9}, {%0,%1,%2,%3};\n"
        : "+f"(c[0]), "+f"(c[1]), "+f"(c[2]), "+f"(c[3])
        : "r"(a0), "r"(a1), "r"(a2), "r"(a3), "r"(b0), "r"(b1));
}

// 3xTF32: acc += lo*hi + hi*lo + hi*hi  (~fp32 product precision)
__device__ __forceinline__ void mma3(float c[4],
                                     const uint32_t ah[4], const uint32_t al[4],
                                     uint32_t bh0, uint32_t bh1,
                                     uint32_t bl0, uint32_t bl1) {
    mma_tf32(c, al[0], al[1], al[2], al[3], bh0, bh1);
    mma_tf32(c, ah[0], ah[1], ah[2], ah[3], bl0, bl1);
    mma_tf32(c, ah[0], ah[1], ah[2], ah[3], bh0, bh1);
}

// ---------------------------------------------------------------------------
__global__ void zero_m_kernel() {
    int i = blockIdx.x * blockDim.x + threadIdx.x;
    int stride = gridDim.x * blockDim.x;
    for (; i < BS_*E_; i += stride) g_M[i] = 0.f;
}

// ---------------------------------------------------------------------------
// Batched projections via 3xTF32 MMA. p in [0,8)->Q head p, [8,16)->K, 16->V.
__global__ void proj_mma_kernel(const float* __restrict__ q, const float* __restrict__ k,
                                const float* __restrict__ v,
                                const float* __restrict__ Wq, const float* __restrict__ bq,
                                const float* __restrict__ Wk, const float* __restrict__ bk,
                                const float* __restrict__ Wv, const float* __restrict__ bv) {
    const int p = blockIdx.y;
    const float* A; const float* W; const float* bias; float* out;
    if (p < 8)       { A = q; W = Wq + (size_t)p*D_*E_;     bias = bq + p*E_;     out = g_Q + (size_t)p*BS_*E_; }
    else if (p < 16) { A = k; W = Wk + (size_t)(p-8)*D_*E_; bias = bk + (p-8)*E_; out = g_K + (size_t)(p-8)*BS_*E_; }
    else             { A = v; W = Wv;                        bias = bv;            out = g_V; }

    __shared__ float As[64*36];   // [row][k]  stride 36 (4-aligned)
    __shared__ float Bs[32*68];   // [k][n]    stride 68 (4-aligned)

    const int tid  = threadIdx.x;
    const int lane = tid & 31;
    const int warp = tid >> 5;
    const int wm = warp >> 1, wn = warp & 1;
    const int grp = lane >> 2, qid = lane & 3;
    const int m0 = blockIdx.x * 64;

    float acc[2][4][4] = {};

    for (int k0 = 0; k0 < D_; k0 += 32) {
        #pragma unroll
        for (int t = 0; t < 4; t++) {
            int f = tid + t*128;
            int r = f >> 3, c = (f & 7) * 4;
            *(float4*)&As[r*36 + c] = *(const float4*)&A[(size_t)(m0 + r)*D_ + k0 + c];
        }
        #pragma unroll
        for (int t = 0; t < 4; t++) {
            int f = tid + t*128;
            int r = f >> 4, c = (f & 15) * 4;
            *(float4*)&Bs[r*68 + c] = *(const float4*)&W[(size_t)(k0 + r)*E_ + c];
        }
        __syncthreads();

        #pragma unroll
        for (int ks = 0; ks < 4; ks++) {
            uint32_t ah[2][4], al[2][4];
            #pragma unroll
            for (int i = 0; i < 2; i++) {
                int row = wm*32 + i*16;
                split_tf32(As[(row+grp  )*36 + ks*8 + qid    ], ah[i][0], al[i][0]);
                split_tf32(As[(row+grp+8)*36 + ks*8 + qid    ], ah[i][1], al[i][1]);
                split_tf32(As[(row+grp  )*36 + ks*8 + qid + 4], ah[i][2], al[i][2]);
                split_tf32(As[(row+grp+8)*36 + ks*8 + qid + 4], ah[i][3], al[i][3]);
            }
            #pragma unroll
            for (int j = 0; j < 4; j++) {
                int col = wn*32 + j*8;
                uint32_t bh0, bl0, bh1, bl1;
                split_tf32(Bs[(ks*8 + qid    )*68 + col + grp], bh0, bl0);
                split_tf32(Bs[(ks*8 + qid + 4)*68 + col + grp], bh1, bl1);
                mma3(acc[0][j], ah[0], al[0], bh0, bh1, bl0, bl1);
                mma3(acc[1][j], ah[1], al[1], bh0, bh1, bl0, bl1);
            }
        }
        __syncthreads();
    }

    #pragma unroll
    for (int i = 0; i < 2; i++) {
        int row0 = m0 + wm*32 + i*16 + grp;
        #pragma unroll
        for (int j = 0; j < 4; j++) {
            int col0 = wn*32 + j*8 + qid*2;
            out[(size_t)row0*E_     + col0    ] = acc[i][j][0] + bias[col0    ];
            out[(size_t)row0*E_     + col0 + 1] = acc[i][j][1] + bias[col0 + 1];
            out[(size_t)(row0+8)*E_ + col0    ] = acc[i][j][2] + bias[col0    ];
            out[(size_t)(row0+8)*E_ + col0 + 1] = acc[i][j][3] + bias[col0 + 1];
        }
    }
}

// ---------------------------------------------------------------------------
// Flash-style causal attention — R1 FFMA version VERBATIM (proven 5e-8).
// 256 threads, 64x64 tiles, per (qtile, b, h). atomicAdd(o/(l*H)) into g_M.
__global__ void attn_kernel() {
    const int qt = blockIdx.x, b = blockIdx.y, h = blockIdx.z;
    extern __shared__ float sm[];
    float* Qs   = sm;              // 64*65
    float* Ks   = Qs + 64*65;
    float* Vs   = Ks + 64*65;
    float* Ss   = Vs + 64*65;
    float* m_sh = Ss + 64*65;      // 64
    float* l_sh = m_sh + 64;       // 64
    float* c_sh = l_sh + 64;       // 64

    const int tid = threadIdx.x;
    const int tx = tid & 15, ty = tid >> 4;
    const float* Qp = g_Q + (((size_t)h*B_ + b)*S_ + (size_t)qt*64)*E_;
    const float* Kp = g_K + ((size_t)h*B_ + b)*S_*E_;
    const float* Vp = g_V + (size_t)b*S_*E_;

    #pragma unroll
    for (int t = 0; t < 16; t++) {
        int f = tid + t*256;
        int r = f >> 6, c = f & 63;
        Qs[r*65 + c] = Qp[r*64 + c];
    }
    if (tid < 64) { m_sh[tid] = -1e30f; l_sh[tid] = 0.f; }

    float o[4][4] = {};
    for (int j = 0; j <= qt; j++) {
        __syncthreads();   // previous PV reads done; init visible on first iter
        #pragma unroll
        for (int t = 0; t < 16; t++) {
            int f = tid + t*256;
            int r = f >> 6, c = f & 63;
            Ks[r*65 + c] = Kp[(size_t)(j*64 + r)*64 + c];
            Vs[r*65 + c] = Vp[(size_t)(j*64 + r)*64 + c];
        }
        __syncthreads();

        float s[4][4] = {};
        #pragma unroll
        for (int kk = 0; kk < 64; kk++) {
            float a[4], bb[4];
            #pragma unroll
            for (int i = 0; i < 4; i++)  a[i]  = Qs[(ty*4+i)*65 + kk];
            #pragma unroll
            for (int jj = 0; jj < 4; jj++) bb[jj] = Ks[(tx*4+jj)*65 + kk];
            #pragma unroll
            for (int i = 0; i < 4; i++)
                #pragma unroll
                for (int jj = 0; jj < 4; jj++)
                    s[i][jj] += a[i]*bb[jj];
        }
        const bool diag = (j == qt);
        #pragma unroll
        for (int i = 0; i < 4; i++)
            #pragma unroll
            for (int jj = 0; jj < 4; jj++) {
                float val = s[i][jj] * 0.125f;           // 1/sqrt(E)
                if (diag && (tx*4+jj) > (ty*4+i)) val = -1e30f;
                Ss[(ty*4+i)*65 + tx*4+jj] = val;
            }
        __syncthreads();

        if (tid < 64) {                                   // online softmax, one row each
            float mold = m_sh[tid];
            float mx = mold;
            for (int c = 0; c < 64; c++) mx = fmaxf(mx, Ss[tid*65 + c]);
            float corr = __expf(mold - mx);
            float sum = 0.f;
            for (int c = 0; c < 64; c++) {
                float pv = __expf(Ss[tid*65 + c] - mx);
                Ss[tid*65 + c] = pv;
                sum += pv;
            }
            l_sh[tid] = l_sh[tid]*corr + sum;
            m_sh[tid] = mx;
            c_sh[tid] = corr;
        }
        __syncthreads();

        #pragma unroll
        for (int i = 0; i < 4; i++) {
            float cf = c_sh[ty*4+i];
            #pragma unroll
            for (int jj = 0; jj < 4; jj++) o[i][jj] *= cf;
        }
        #pragma unroll
        for (int kk = 0; kk < 64; kk++) {
            float pp[4], vv[4];
            #pragma unroll
            for (int i = 0; i < 4; i++)   pp[i]  = Ss[(ty*4+i)*65 + kk];
            #pragma unroll
            for (int jj = 0; jj < 4; jj++) vv[jj] = Vs[kk*65 + tx*4+jj];
            #pragma unroll
            for (int i = 0; i < 4; i++)
                #pragma unroll
                for (int jj = 0; jj < 4; jj++)
                    o[i][jj] += pp[i]*vv[jj];
        }
    }
    __syncthreads();
    #pragma unroll
    for (int i = 0; i < 4; i++) {
        int r = ty*4 + i;
        float inv = 1.f / (l_sh[r] * (float)H_);
        #pragma unroll
        for (int jj = 0; jj < 4; jj++)
            atomicAdd(&g_M[((size_t)b*S_ + qt*64 + r)*E_ + tx*4 + jj], o[i][jj]*inv);
    }
}

// ---------------------------------------------------------------------------
// Final linear: G = g_M[512,512] @ Wf[512,512]  (scramble is identity; see R1)
__global__ void gemm_g_kernel(const float* __restrict__ Wf) {
    __shared__ float As[64*36];
    __shared__ float Bs[32*68];
    const int tid  = threadIdx.x;
    const int lane = tid & 31;
    const int warp = tid >> 5;
    const int wm = warp >> 1, wn = warp & 1;
    const int grp = lane >> 2, qid = lane & 3;
    const int m0 = blockIdx.x * 64, n0 = blockIdx.y * 64;

    float acc[2][4][4] = {};

    for (int k0 = 0; k0 < 512; k0 += 32) {
        #pragma unroll
        for (int t = 0; t < 4; t++) {
            int f = tid + t*128;
            int r = f >> 3, c = (f & 7) * 4;
            *(float4*)&As[r*36 + c] = *(const float4*)&g_M[(size_t)(m0 + r)*512 + k0 + c];
        }
        #pragma unroll
        for (int t = 0; t < 4; t++) {
            int f = tid + t*128;
            int r = f >> 4, c = (f & 15) * 4;
            *(float4*)&Bs[r*68 + c] = *(const float4*)&Wf[(size_t)(k0 + r)*512 + n0 + c];
        }
        __syncthreads();

        #pragma unroll
        for (int ks = 0; ks < 4; ks++) {
            uint32_t ah[2][4], al[2][4];
            #pragma unroll
            for (int i = 0; i < 2; i++) {
                int row = wm*32 + i*16;
                split_tf32(As[(row+grp  )*36 + ks*8 + qid    ], ah[i][0], al[i][0]);
                split_tf32(As[(row+grp+8)*36 + ks*8 + qid    ], ah[i][1], al[i][1]);
                split_tf32(As[(row+grp  )*36 + ks*8 + qid + 4], ah[i][2], al[i][2]);
                split_tf32(As[(row+grp+8)*36 + ks*8 + qid + 4], ah[i][3], al[i][3]);
            }
            #pragma unroll
            for (int jn = 0; jn < 4; jn++) {
                int col = wn*32 + jn*8;
                uint32_t bh0, bl0, bh1, bl1;
                split_tf32(Bs[(ks*8 + qid    )*68 + col + grp], bh0, bl0);
                split_tf32(Bs[(ks*8 + qid + 4)*68 + col + grp], bh1, bl1);
                mma3(acc[0][jn], ah[0], al[0], bh0, bh1, bl0, bl1);
                mma3(acc[1][jn], ah[1], al[1], bh0, bh1, bl0, bl1);
            }
        }
        __syncthreads();
    }

    #pragma unroll
    for (int i = 0; i < 2; i++) {
        int row0 = m0 + wm*32 + i*16 + grp;
        #pragma unroll
        for (int jn = 0; jn < 4; jn++) {
            int col0 = n0 + wn*32 + jn*8 + qid*2;
            g_G[(size_t)row0*512     + col0    ] = acc[i][jn][0];
            g_G[(size_t)row0*512     + col0 + 1] = acc[i][jn][1];
            g_G[(size_t)(row0+8)*512 + col0    ] = acc[i][jn][2];
            g_G[(size_t)(row0+8)*512 + col0 + 1] = acc[i][jn][3];
        }
    }
}

// ---------------------------------------------------------------------------
__global__ void ln_kernel(const float* __restrict__ query, const float* __restrict__ bf,
                          const float* __restrict__ lnw, const float* __restrict__ lnb,
                          float* __restrict__ out) {
    const int row  = blockIdx.x;
    const int bb   = row >> 10;
    const int r128 = row & 127;
    const float* g    = g_G + ((size_t)bb*128 + r128)*D_;
    const float* qrow = query + (size_t)row*D_;
    const int tid = threadIdx.x;
    float x[4];
    float sum = 0.f;
    #pragma unroll
    for (int t = 0; t < 4; t++) {
        int c = tid + t*128;
        x[t] = g[c] + bf[c] + qrow[c];
        sum += x[t];
    }
    __shared__ float red[4];
    __shared__ float red2[4];
    #pragma unroll
    for (int off = 16; off; off >>= 1) sum += __shfl_xor_sync(0xffffffffu, sum, off);
    if ((tid & 31) == 0) red[tid >> 5] = sum;
    __syncthreads();
    float mean = (red[0]+red[1]+red[2]+red[3]) * (1.f/512.f);

    float sq = 0.f;
    #pragma unroll
    for (int t = 0; t < 4; t++) { float d = x[t] - mean; sq += d*d; }
    #pragma unroll
    for (int off = 16; off; off >>= 1) sq += __shfl_xor_sync(0xffffffffu, sq, off);
    if ((tid & 31) == 0) red2[tid >> 5] = sq;
    __syncthreads();
    float var_num = red2[0]+red2[1]+red2[2]+red2[3];
    float stdv = sqrtf(var_num * (1.f/511.f));
    float inv  = 1.f / (stdv + 1e-6f);
    #pragma unroll
    for (int t = 0; t < 4; t++) {
        int c = tid + t*128;
        out[(size_t)row*D_ + c] = lnw[c]*(x[t]-mean)*inv + lnb[c];
    }
}

// ---------------------------------------------------------------------------
extern "C" void kernel_launch(void* const* d_in, const int* in_sizes, int n_in,
                              void* d_out, int out_size) {
    const float* query = (const float*)d_in[0];
    const float* key   = (const float*)d_in[1];
    const float* value = (const float*)d_in[2];
    // d_in[3] = mask (tril, handled analytically)
    const float* Wq = (const float*)d_in[4];
    const float* bq = (const float*)d_in[5];
    const float* Wk = (const float*)d_in[6];
    const float* bk = (const float*)d_in[7];
    const float* Wv = (const float*)d_in[8];
    const float* bv = (const float*)d_in[9];
    const float* Wf = (const float*)d_in[10];
    const float* bf = (const float*)d_in[11];
    const float* lnw = (const float*)d_in[12];
    const float* lnb = (const float*)d_in[13];
    float* out = (float*)d_out;

    // R1 attn smem: 4*64*65 + 3*64 floats = 67328 B
    const size_t attn_smem = (size_t)(4*64*65 + 3*64) * sizeof(float);
    cudaFuncSetAttribute(attn_kernel, cudaFuncAttributeMaxDynamicSharedMemorySize,
                         (int)attn_smem);

    zero_m_kernel<<<64, 256>>>();
    proj_mma_kernel<<<dim3(BS_/64, 17), 128>>>(query, key, value, Wq, bq, Wk, bk, Wv, bv);
    attn_kernel<<<dim3(S_/64, B_, H_), 256, attn_smem>>>();
    gemm_g_kernel<<<dim3(8, 8), 128>>>(Wf);
    ln_kernel<<<BS_, 128>>>(query, bf, lnw, lnb, out);
}

// round 8
// speedup vs baseline: 1.1091x; 1.0249x over previous
#include <cuda_runtime.h>
#include <math.h>
#include <stdint.h>

#define B_ 4
#define S_ 1024
#define D_ 512
#define H_ 8
#define E_ 64
#define BS_ (B_*S_)

// Scratch (device globals — no runtime allocation allowed)
__device__ float g_Q[H_*BS_*E_];     // [H][B*S][E]
__device__ float g_K[H_*BS_*E_];
__device__ float g_V[BS_*E_];
__device__ float g_M[BS_*E_];        // mean-over-heads accumulator
__device__ float g_G[B_*128*D_];     // final-GEMM output [512][512]

// ---------------------------------------------------------------------------
__device__ __forceinline__ uint32_t f2tf32(float x) {
    uint32_t r;
    asm("cvt.rna.tf32.f32 %0, %1;" : "=r"(r) : "f"(x));
    return r;
}
__device__ __forceinline__ void split_tf32(float x, uint32_t& hi, uint32_t& lo) {
    hi = f2tf32(x);
    lo = f2tf32(x - __uint_as_float(hi));
}

// D += A(16x8,row) * B(8x8,col)   tf32, fp32 accum
__device__ __forceinline__ void mma_tf32(float c[4],
                                         uint32_t a0, uint32_t a1, uint32_t a2, uint32_t a3,
                                         uint32_t b0, uint32_t b1) {
    asm volatile(
        "mma.sync.aligned.m16n8k8.row.col.f32.tf32.tf32.f32 "
        "{%0,%1,%2,%3}, {%4,%5,%6,%7}, {%8,%9}, {%0,%1,%2,%3};\n"
        : "+f"(c[0]), "+f"(c[1]), "+f"(c[2]), "+f"(c[3])
        : "r"(a0), "r"(a1), "r"(a2), "r"(a3), "r"(b0), "r"(b1));
}

// 3xTF32: acc += lo*hi + hi*lo + hi*hi  (~fp32 product precision)
__device__ __forceinline__ void mma3(float c[4],
                                     const uint32_t ah[4], const uint32_t al[4],
                                     uint32_t bh0, uint32_t bh1,
                                     uint32_t bl0, uint32_t bl1) {
    mma_tf32(c, al[0], al[1], al[2], al[3], bh0, bh1);
    mma_tf32(c, ah[0], ah[1], ah[2], ah[3], bl0, bl1);
    mma_tf32(c, ah[0], ah[1], ah[2], ah[3], bh0, bh1);
}

// ---------------------------------------------------------------------------
__global__ void zero_m_kernel() {
    int i = blockIdx.x * blockDim.x + threadIdx.x;
    int stride = gridDim.x * blockDim.x;
    for (; i < BS_*E_; i += stride) g_M[i] = 0.f;
}

// ---------------------------------------------------------------------------
// Batched projections via 3xTF32 MMA (PROVEN). p<8: Q head p; p<16: K; 16: V.
__global__ void proj_mma_kernel(const float* __restrict__ q, const float* __restrict__ k,
                                const float* __restrict__ v,
                                const float* __restrict__ Wq, const float* __restrict__ bq,
                                const float* __restrict__ Wk, const float* __restrict__ bk,
                                const float* __restrict__ Wv, const float* __restrict__ bv) {
    const int p = blockIdx.y;
    const float* A; const float* W; const float* bias; float* out;
    if (p < 8)       { A = q; W = Wq + (size_t)p*D_*E_;     bias = bq + p*E_;     out = g_Q + (size_t)p*BS_*E_; }
    else if (p < 16) { A = k; W = Wk + (size_t)(p-8)*D_*E_; bias = bk + (p-8)*E_; out = g_K + (size_t)(p-8)*BS_*E_; }
    else             { A = v; W = Wv;                        bias = bv;            out = g_V; }

    __shared__ float As[64*36];   // [row][k]  stride 36 (4-aligned)
    __shared__ float Bs[32*68];   // [k][n]    stride 68 (4-aligned)

    const int tid  = threadIdx.x;
    const int lane = tid & 31;
    const int warp = tid >> 5;
    const int wm = warp >> 1, wn = warp & 1;
    const int grp = lane >> 2, qid = lane & 3;
    const int m0 = blockIdx.x * 64;

    float acc[2][4][4] = {};

    for (int k0 = 0; k0 < D_; k0 += 32) {
        #pragma unroll
        for (int t = 0; t < 4; t++) {
            int f = tid + t*128;
            int r = f >> 3, c = (f & 7) * 4;
            *(float4*)&As[r*36 + c] = *(const float4*)&A[(size_t)(m0 + r)*D_ + k0 + c];
        }
        #pragma unroll
        for (int t = 0; t < 4; t++) {
            int f = tid + t*128;
            int r = f >> 4, c = (f & 15) * 4;
            *(float4*)&Bs[r*68 + c] = *(const float4*)&W[(size_t)(k0 + r)*E_ + c];
        }
        __syncthreads();

        #pragma unroll
        for (int ks = 0; ks < 4; ks++) {
            uint32_t ah[2][4], al[2][4];
            #pragma unroll
            for (int i = 0; i < 2; i++) {
                int row = wm*32 + i*16;
                split_tf32(As[(row+grp  )*36 + ks*8 + qid    ], ah[i][0], al[i][0]);
                split_tf32(As[(row+grp+8)*36 + ks*8 + qid    ], ah[i][1], al[i][1]);
                split_tf32(As[(row+grp  )*36 + ks*8 + qid + 4], ah[i][2], al[i][2]);
                split_tf32(As[(row+grp+8)*36 + ks*8 + qid + 4], ah[i][3], al[i][3]);
            }
            #pragma unroll
            for (int j = 0; j < 4; j++) {
                int col = wn*32 + j*8;
                uint32_t bh0, bl0, bh1, bl1;
                split_tf32(Bs[(ks*8 + qid    )*68 + col + grp], bh0, bl0);
                split_tf32(Bs[(ks*8 + qid + 4)*68 + col + grp], bh1, bl1);
                mma3(acc[0][j], ah[0], al[0], bh0, bh1, bl0, bl1);
                mma3(acc[1][j], ah[1], al[1], bh0, bh1, bl0, bl1);
            }
        }
        __syncthreads();
    }

    #pragma unroll
    for (int i = 0; i < 2; i++) {
        int row0 = m0 + wm*32 + i*16 + grp;
        #pragma unroll
        for (int j = 0; j < 4; j++) {
            int col0 = wn*32 + j*8 + qid*2;
            out[(size_t)row0*E_     + col0    ] = acc[i][j][0] + bias[col0    ];
            out[(size_t)row0*E_     + col0 + 1] = acc[i][j][1] + bias[col0 + 1];
            out[(size_t)(row0+8)*E_ + col0    ] = acc[i][j][2] + bias[col0    ];
            out[(size_t)(row0+8)*E_ + col0 + 1] = acc[i][j][3] + bias[col0 + 1];
        }
    }
}

// ---------------------------------------------------------------------------
// MIRROR-HYBRID flash attention: loads / QK^T FFMA / mask / softmax are the
// R5 PASSING kernel VERBATIM (strides 65, 256 threads). Only PV + correction
// + epilogue switch to 3xTF32 MMA (8 warps, 16x32 tiles each).
__global__ void attn_kernel() {
    const int qt = blockIdx.x, b = blockIdx.y, h = blockIdx.z;
    extern __shared__ float sm[];
    float* Qs   = sm;              // 64*65
    float* Ks   = Qs + 64*65;
    float* Vs   = Ks + 64*65;      // [key][e] stride 65 (k-major for PV MMA)
    float* Ss   = Vs + 64*65;      // scores -> P
    float* m_sh = Ss + 64*65;      // 64
    float* l_sh = m_sh + 64;       // 64
    float* c_sh = l_sh + 64;       // 64

    const int tid = threadIdx.x;
    const int tx = tid & 15, ty = tid >> 4;      // FFMA QK mapping (R1/R5)
    const int lane = tid & 31;
    const int warp = tid >> 5;                   // 0..7
    const int wm = warp >> 1, wn = warp & 1;     // PV MMA: rows wm*16+, cols wn*32+
    const int grp = lane >> 2, qid = lane & 3;

    const float* Qp = g_Q + (((size_t)h*B_ + b)*S_ + (size_t)qt*64)*E_;
    const float* Kp = g_K + ((size_t)h*B_ + b)*S_*E_;
    const float* Vp = g_V + (size_t)b*S_*E_;

    #pragma unroll
    for (int t = 0; t < 16; t++) {
        int f = tid + t*256;
        int r = f >> 6, c = f & 63;
        Qs[r*65 + c] = Qp[r*64 + c];
    }
    if (tid < 64) { m_sh[tid] = -1e30f; l_sh[tid] = 0.f; }

    float acc_o[4][4] = {};                      // PV MMA accumulator (C layout)

    for (int j = 0; j <= qt; j++) {
        __syncthreads();   // previous PV reads done; init visible on first iter
        #pragma unroll
        for (int t = 0; t < 16; t++) {
            int f = tid + t*256;
            int r = f >> 6, c = f & 63;
            Ks[r*65 + c] = Kp[(size_t)(j*64 + r)*64 + c];
            Vs[r*65 + c] = Vp[(size_t)(j*64 + r)*64 + c];
        }
        __syncthreads();

        // ---- S = Q @ K^T  (R5 FFMA VERBATIM) ----
        float s[4][4] = {};
        #pragma unroll
        for (int kk = 0; kk < 64; kk++) {
            float a[4], bb[4];
            #pragma unroll
            for (int i = 0; i < 4; i++)  a[i]  = Qs[(ty*4+i)*65 + kk];
            #pragma unroll
            for (int jj = 0; jj < 4; jj++) bb[jj] = Ks[(tx*4+jj)*65 + kk];
            #pragma unroll
            for (int i = 0; i < 4; i++)
                #pragma unroll
                for (int jj = 0; jj < 4; jj++)
                    s[i][jj] += a[i]*bb[jj];
        }
        const bool diag = (j == qt);
        #pragma unroll
        for (int i = 0; i < 4; i++)
            #pragma unroll
            for (int jj = 0; jj < 4; jj++) {
                float val = s[i][jj] * 0.125f;
                if (diag && (tx*4+jj) > (ty*4+i)) val = -1e30f;
                Ss[(ty*4+i)*65 + tx*4+jj] = val;
            }
        __syncthreads();

        // ---- online softmax (R5 VERBATIM) ----
        if (tid < 64) {
            float mold = m_sh[tid];
            float mx = mold;
            for (int c = 0; c < 64; c++) mx = fmaxf(mx, Ss[tid*65 + c]);
            float corr = __expf(mold - mx);
            float sum = 0.f;
            for (int c = 0; c < 64; c++) {
                float pv = __expf(Ss[tid*65 + c] - mx);
                Ss[tid*65 + c] = pv;
                sum += pv;
            }
            l_sh[tid] = l_sh[tid]*corr + sum;
            m_sh[tid] = mx;
            c_sh[tid] = corr;
        }
        __syncthreads();

        // ---- O = O*corr + P @ V  via 3xTF32 MMA (8 warps, 16x32 each) ----
        {
            int r0 = wm*16 + grp;
            float cA = c_sh[r0], cB = c_sh[r0 + 8];
            #pragma unroll
            for (int jn = 0; jn < 4; jn++) {
                acc_o[jn][0] *= cA; acc_o[jn][1] *= cA;
                acc_o[jn][2] *= cB; acc_o[jn][3] *= cB;
            }
            #pragma unroll
            for (int ks = 0; ks < 8; ks++) {
                uint32_t ah[4], al[4];
                split_tf32(Ss[(r0    )*65 + ks*8 + qid    ], ah[0], al[0]);
                split_tf32(Ss[(r0 + 8)*65 + ks*8 + qid    ], ah[1], al[1]);
                split_tf32(Ss[(r0    )*65 + ks*8 + qid + 4], ah[2], al[2]);
                split_tf32(Ss[(r0 + 8)*65 + ks*8 + qid + 4], ah[3], al[3]);
                #pragma unroll
                for (int jn = 0; jn < 4; jn++) {
                    int col = wn*32 + jn*8;
                    uint32_t bh0, bl0, bh1, bl1;
                    split_tf32(Vs[(ks*8 + qid    )*65 + col + grp], bh0, bl0);
                    split_tf32(Vs[(ks*8 + qid + 4)*65 + col + grp], bh1, bl1);
                    mma3(acc_o[jn], ah, al, bh0, bh1, bl0, bl1);
                }
            }
        }
    }
    __syncthreads();

    // ---- epilogue: MMA C layout ----
    {
        int r0 = wm*16 + grp;
        float invA = 1.f / (l_sh[r0    ] * (float)H_);
        float invB = 1.f / (l_sh[r0 + 8] * (float)H_);
        float* dst = &g_M[((size_t)b*S_ + qt*64)*E_];
        #pragma unroll
        for (int jn = 0; jn < 4; jn++) {
            int c0 = wn*32 + jn*8 + qid*2;
            atomicAdd(&dst[(size_t)(r0    )*E_ + c0    ], acc_o[jn][0]*invA);
            atomicAdd(&dst[(size_t)(r0    )*E_ + c0 + 1], acc_o[jn][1]*invA);
            atomicAdd(&dst[(size_t)(r0 + 8)*E_ + c0    ], acc_o[jn][2]*invB);
            atomicAdd(&dst[(size_t)(r0 + 8)*E_ + c0 + 1], acc_o[jn][3]*invB);
        }
    }
}

// ---------------------------------------------------------------------------
// Final linear: G = g_M[512,512] @ Wf[512,512]  (scramble is identity; PROVEN)
__global__ void gemm_g_kernel(const float* __restrict__ Wf) {
    __shared__ float As[64*36];
    __shared__ float Bs[32*68];
    const int tid  = threadIdx.x;
    const int lane = tid & 31;
    const int warp = tid >> 5;
    const int wm = warp >> 1, wn = warp & 1;
    const int grp = lane >> 2, qid = lane & 3;
    const int m0 = blockIdx.x * 64, n0 = blockIdx.y * 64;

    float acc[2][4][4] = {};

    for (int k0 = 0; k0 < 512; k0 += 32) {
        #pragma unroll
        for (int t = 0; t < 4; t++) {
            int f = tid + t*128;
            int r = f >> 3, c = (f & 7) * 4;
            *(float4*)&As[r*36 + c] = *(const float4*)&g_M[(size_t)(m0 + r)*512 + k0 + c];
        }
        #pragma unroll
        for (int t = 0; t < 4; t++) {
            int f = tid + t*128;
            int r = f >> 4, c = (f & 15) * 4;
            *(float4*)&Bs[r*68 + c] = *(const float4*)&Wf[(size_t)(k0 + r)*512 + n0 + c];
        }
        __syncthreads();

        #pragma unroll
        for (int ks = 0; ks < 4; ks++) {
            uint32_t ah[2][4], al[2][4];
            #pragma unroll
            for (int i = 0; i < 2; i++) {
                int row = wm*32 + i*16;
                split_tf32(As[(row+grp  )*36 + ks*8 + qid    ], ah[i][0], al[i][0]);
                split_tf32(As[(row+grp+8)*36 + ks*8 + qid    ], ah[i][1], al[i][1]);
                split_tf32(As[(row+grp  )*36 + ks*8 + qid + 4], ah[i][2], al[i][2]);
                split_tf32(As[(row+grp+8)*36 + ks*8 + qid + 4], ah[i][3], al[i][3]);
            }
            #pragma unroll
            for (int jn = 0; jn < 4; jn++) {
                int col = wn*32 + jn*8;
                uint32_t bh0, bl0, bh1, bl1;
                split_tf32(Bs[(ks*8 + qid    )*68 + col + grp], bh0, bl0);
                split_tf32(Bs[(ks*8 + qid + 4)*68 + col + grp], bh1, bl1);
                mma3(acc[0][jn], ah[0], al[0], bh0, bh1, bl0, bl1);
                mma3(acc[1][jn], ah[1], al[1], bh0, bh1, bl0, bl1);
            }
        }
        __syncthreads();
    }

    #pragma unroll
    for (int i = 0; i < 2; i++) {
        int row0 = m0 + wm*32 + i*16 + grp;
        #pragma unroll
        for (int jn = 0; jn < 4; jn++) {
            int col0 = n0 + wn*32 + jn*8 + qid*2;
            g_G[(size_t)row0*512     + col0    ] = acc[i][jn][0];
            g_G[(size_t)row0*512     + col0 + 1] = acc[i][jn][1];
            g_G[(size_t)(row0+8)*512 + col0    ] = acc[i][jn][2];
            g_G[(size_t)(row0+8)*512 + col0 + 1] = acc[i][jn][3];
        }
    }
}

// ---------------------------------------------------------------------------
__global__ void ln_kernel(const float* __restrict__ query, const float* __restrict__ bf,
                          const float* __restrict__ lnw, const float* __restrict__ lnb,
                          float* __restrict__ out) {
    const int row  = blockIdx.x;
    const int bb   = row >> 10;
    const int r128 = row & 127;
    const float* g    = g_G + ((size_t)bb*128 + r128)*D_;
    const float* qrow = query + (size_t)row*D_;
    const int tid = threadIdx.x;
    float x[4];
    float sum = 0.f;
    #pragma unroll
    for (int t = 0; t < 4; t++) {
        int c = tid + t*128;
        x[t] = g[c] + bf[c] + qrow[c];
        sum += x[t];
    }
    __shared__ float red[4];
    __shared__ float red2[4];
    #pragma unroll
    for (int off = 16; off; off >>= 1) sum += __shfl_xor_sync(0xffffffffu, sum, off);
    if ((tid & 31) == 0) red[tid >> 5] = sum;
    __syncthreads();
    float mean = (red[0]+red[1]+red[2]+red[3]) * (1.f/512.f);

    float sq = 0.f;
    #pragma unroll
    for (int t = 0; t < 4; t++) { float d = x[t] - mean; sq += d*d; }
    #pragma unroll
    for (int off = 16; off; off >>= 1) sq += __shfl_xor_sync(0xffffffffu, sq, off);
    if ((tid & 31) == 0) red2[tid >> 5] = sq;
    __syncthreads();
    float var_num = red2[0]+red2[1]+red2[2]+red2[3];
    float stdv = sqrtf(var_num * (1.f/511.f));
    float inv  = 1.f / (stdv + 1e-6f);
    #pragma unroll
    for (int t = 0; t < 4; t++) {
        int c = tid + t*128;
        out[(size_t)row*D_ + c] = lnw[c]*(x[t]-mean)*inv + lnb[c];
    }
}

// ---------------------------------------------------------------------------
extern "C" void kernel_launch(void* const* d_in, const int* in_sizes, int n_in,
                              void* d_out, int out_size) {
    const float* query = (const float*)d_in[0];
    const float* key   = (const float*)d_in[1];
    const float* value = (const float*)d_in[2];
    // d_in[3] = mask (tril, handled analytically)
    const float* Wq = (const float*)d_in[4];
    const float* bq = (const float*)d_in[5];
    const float* Wk = (const float*)d_in[6];
    const float* bk = (const float*)d_in[7];
    const float* Wv = (const float*)d_in[8];
    const float* bv = (const float*)d_in[9];
    const float* Wf = (const float*)d_in[10];
    const float* bf = (const float*)d_in[11];
    const float* lnw = (const float*)d_in[12];
    const float* lnb = (const float*)d_in[13];
    float* out = (float*)d_out;

    // attn smem: 4*64*65 + 3*64 floats = 67328 B  (R5 layout)
    const size_t attn_smem = (size_t)(4*64*65 + 3*64) * sizeof(float);
    cudaFuncSetAttribute(attn_kernel, cudaFuncAttributeMaxDynamicSharedMemorySize,
                         (int)attn_smem);

    zero_m_kernel<<<64, 256>>>();
    proj_mma_kernel<<<dim3(BS_/64, 17), 128>>>(query, key, value, Wq, bq, Wk, bk, Wv, bv);
    attn_kernel<<<dim3(S_/64, B_, H_), 256, attn_smem>>>();
    gemm_g_kernel<<<dim3(8, 8), 128>>>(Wf);
    ln_kernel<<<BS_, 128>>>(query, bf, lnw, lnb, out);
}

// round 9
// speedup vs baseline: 1.1403x; 1.0281x over previous
#include <cuda_runtime.h>
#include <math.h>
#include <stdint.h>

#define B_ 4
#define S_ 1024
#define D_ 512
#define H_ 8
#define E_ 64
#define BS_ (B_*S_)

// Scratch (device globals — no runtime allocation allowed)
__device__ float g_Q[H_*BS_*E_];     // [H][B*S][E]
__device__ float g_K[H_*BS_*E_];
__device__ float g_V[BS_*E_];
__device__ float g_M[BS_*E_];        // mean-over-heads accumulator
__device__ float g_G[B_*128*D_];     // final-GEMM output [512][512]

// ---------------------------------------------------------------------------
__device__ __forceinline__ uint32_t f2tf32(float x) {
    uint32_t r;
    asm("cvt.rna.tf32.f32 %0, %1;" : "=r"(r) : "f"(x));
    return r;
}
__device__ __forceinline__ void split_tf32(float x, uint32_t& hi, uint32_t& lo) {
    hi = f2tf32(x);
    lo = f2tf32(x - __uint_as_float(hi));
}

// D += A(16x8,row) * B(8x8,col)   tf32, fp32 accum
__device__ __forceinline__ void mma_tf32(float c[4],
                                         uint32_t a0, uint32_t a1, uint32_t a2, uint32_t a3,
                                         uint32_t b0, uint32_t b1) {
    asm volatile(
        "mma.sync.aligned.m16n8k8.row.col.f32.tf32.tf32.f32 "
        "{%0,%1,%2,%3}, {%4,%5,%6,%7}, {%8,%9}, {%0,%1,%2,%3};\n"
        : "+f"(c[0]), "+f"(c[1]), "+f"(c[2]), "+f"(c[3])
        : "r"(a0), "r"(a1), "r"(a2), "r"(a3), "r"(b0), "r"(b1));
}

// 3xTF32: acc += lo*hi + hi*lo + hi*hi  (~fp32 product precision)
__device__ __forceinline__ void mma3(float c[4],
                                     const uint32_t ah[4], const uint32_t al[4],
                                     uint32_t bh0, uint32_t bh1,
                                     uint32_t bl0, uint32_t bl1) {
    mma_tf32(c, al[0], al[1], al[2], al[3], bh0, bh1);
    mma_tf32(c, ah[0], ah[1], ah[2], ah[3], bl0, bl1);
    mma_tf32(c, ah[0], ah[1], ah[2], ah[3], bh0, bh1);
}

// ---------------------------------------------------------------------------
__global__ void zero_m_kernel() {
    int i = blockIdx.x * blockDim.x + threadIdx.x;
    int stride = gridDim.x * blockDim.x;
    for (; i < BS_*E_; i += stride) g_M[i] = 0.f;
}

// ---------------------------------------------------------------------------
// Batched projections via 3xTF32 MMA (PROVEN). p<8: Q head p; p<16: K; 16: V.
__global__ void proj_mma_kernel(const float* __restrict__ q, const float* __restrict__ k,
                                const float* __restrict__ v,
                                const float* __restrict__ Wq, const float* __restrict__ bq,
                                const float* __restrict__ Wk, const float* __restrict__ bk,
                                const float* __restrict__ Wv, const float* __restrict__ bv) {
    const int p = blockIdx.y;
    const float* A; const float* W; const float* bias; float* out;
    if (p < 8)       { A = q; W = Wq + (size_t)p*D_*E_;     bias = bq + p*E_;     out = g_Q + (size_t)p*BS_*E_; }
    else if (p < 16) { A = k; W = Wk + (size_t)(p-8)*D_*E_; bias = bk + (p-8)*E_; out = g_K + (size_t)(p-8)*BS_*E_; }
    else             { A = v; W = Wv;                        bias = bv;            out = g_V; }

    __shared__ float As[64*36];   // [row][k]  64x32 chunk, stride 36 OK (32<36)
    __shared__ float Bs[32*68];   // [k][n]    stride 68

    const int tid  = threadIdx.x;
    const int lane = tid & 31;
    const int warp = tid >> 5;
    const int wm = warp >> 1, wn = warp & 1;
    const int grp = lane >> 2, qid = lane & 3;
    const int m0 = blockIdx.x * 64;

    float acc[2][4][4] = {};

    for (int k0 = 0; k0 < D_; k0 += 32) {
        #pragma unroll
        for (int t = 0; t < 4; t++) {
            int f = tid + t*128;
            int r = f >> 3, c = (f & 7) * 4;
            *(float4*)&As[r*36 + c] = *(const float4*)&A[(size_t)(m0 + r)*D_ + k0 + c];
        }
        #pragma unroll
        for (int t = 0; t < 4; t++) {
            int f = tid + t*128;
            int r = f >> 4, c = (f & 15) * 4;
            *(float4*)&Bs[r*68 + c] = *(const float4*)&W[(size_t)(k0 + r)*E_ + c];
        }
        __syncthreads();

        #pragma unroll
        for (int ks = 0; ks < 4; ks++) {
            uint32_t ah[2][4], al[2][4];
            #pragma unroll
            for (int i = 0; i < 2; i++) {
                int row = wm*32 + i*16;
                split_tf32(As[(row+grp  )*36 + ks*8 + qid    ], ah[i][0], al[i][0]);
                split_tf32(As[(row+grp+8)*36 + ks*8 + qid    ], ah[i][1], al[i][1]);
                split_tf32(As[(row+grp  )*36 + ks*8 + qid + 4], ah[i][2], al[i][2]);
                split_tf32(As[(row+grp+8)*36 + ks*8 + qid + 4], ah[i][3], al[i][3]);
            }
            #pragma unroll
            for (int j = 0; j < 4; j++) {
                int col = wn*32 + j*8;
                uint32_t bh0, bl0, bh1, bl1;
                split_tf32(Bs[(ks*8 + qid    )*68 + col + grp], bh0, bl0);
                split_tf32(Bs[(ks*8 + qid + 4)*68 + col + grp], bh1, bl1);
                mma3(acc[0][j], ah[0], al[0], bh0, bh1, bl0, bl1);
                mma3(acc[1][j], ah[1], al[1], bh0, bh1, bl0, bl1);
            }
        }
        __syncthreads();
    }

    #pragma unroll
    for (int i = 0; i < 2; i++) {
        int row0 = m0 + wm*32 + i*16 + grp;
        #pragma unroll
        for (int j = 0; j < 4; j++) {
            int col0 = wn*32 + j*8 + qid*2;
            out[(size_t)row0*E_     + col0    ] = acc[i][j][0] + bias[col0    ];
            out[(size_t)row0*E_     + col0 + 1] = acc[i][j][1] + bias[col0 + 1];
            out[(size_t)(row0+8)*E_ + col0    ] = acc[i][j][2] + bias[col0    ];
            out[(size_t)(row0+8)*E_ + col0 + 1] = acc[i][j][3] + bias[col0 + 1];
        }
    }
}

// ---------------------------------------------------------------------------
// Full-MMA flash attention. ROOT-CAUSE FIX: Qs stride 68 (>= 64 columns!).
// The R2/R4/R6/R7 failures were Qs stride 33/36 with a 64-wide tile: rows
// overlapped in smem, corrupting Q. All tiles now stride 68.
// 256 threads, 8 warps: warp tile rows wm*16 (+8), cols wn*32.
__global__ void attn_kernel() {
    const int qt = blockIdx.x, b = blockIdx.y, h = blockIdx.z;
    extern __shared__ float sm[];
    float* Qs = sm;                  // 64*68 [q][e]
    float* Kt = Qs + 64*68;          // 64*68 [e][key]  (B operand for QK^T)
    float* Vs = Kt + 64*68;          // 64*68 [key][e]  (B operand for PV)
    float* Ss = Vs + 64*68;          // 64*68 scores -> P
    float* m_sh = Ss + 64*68;
    float* l_sh = m_sh + 64;
    float* c_sh = l_sh + 64;

    const int tid  = threadIdx.x;
    const int lane = tid & 31;
    const int warp = tid >> 5;                   // 0..7
    const int wm = warp >> 1, wn = warp & 1;
    const int grp = lane >> 2, qid = lane & 3;
    const int r0 = wm*16 + grp;                  // this thread's C rows: r0, r0+8

    const float* Qp = g_Q + (((size_t)h*B_ + b)*S_ + (size_t)qt*64)*E_;
    const float* Kp = g_K + ((size_t)h*B_ + b)*S_*E_;
    const float* Vp = g_V + (size_t)b*S_*E_;

    #pragma unroll
    for (int t = 0; t < 4; t++) {
        int f = tid + t*256;
        int r = f >> 4, c = (f & 15) * 4;
        *(float4*)&Qs[r*68 + c] = *(const float4*)&Qp[(size_t)r*64 + c];
    }
    if (tid < 64) { m_sh[tid] = -1e30f; l_sh[tid] = 0.f; }

    float acc_o[4][4] = {};                      // PV accumulator (C layout)

    for (int j = 0; j <= qt; j++) {
        __syncthreads();   // prev PV reads done; Qs/init visible on iter 0
        #pragma unroll
        for (int t = 0; t < 4; t++) {
            int f = tid + t*256;
            int r = f >> 4, c = (f & 15) * 4;   // r = key row, c = e base
            float4 kv = *(const float4*)&Kp[(size_t)(j*64 + r)*64 + c];
            Kt[(c+0)*68 + r] = kv.x;            // transpose: [e][key]
            Kt[(c+1)*68 + r] = kv.y;
            Kt[(c+2)*68 + r] = kv.z;
            Kt[(c+3)*68 + r] = kv.w;
            *(float4*)&Vs[r*68 + c] = *(const float4*)&Vp[(size_t)(j*64 + r)*64 + c];
        }
        __syncthreads();

        // ---- S = Q @ K^T via 3xTF32 MMA ----
        float acc_s[4][4] = {};
        #pragma unroll
        for (int ks = 0; ks < 8; ks++) {
            uint32_t ah[4], al[4];
            split_tf32(Qs[(r0    )*68 + ks*8 + qid    ], ah[0], al[0]);
            split_tf32(Qs[(r0 + 8)*68 + ks*8 + qid    ], ah[1], al[1]);
            split_tf32(Qs[(r0    )*68 + ks*8 + qid + 4], ah[2], al[2]);
            split_tf32(Qs[(r0 + 8)*68 + ks*8 + qid + 4], ah[3], al[3]);
            #pragma unroll
            for (int jn = 0; jn < 4; jn++) {
                int col = wn*32 + jn*8;
                uint32_t bh0, bl0, bh1, bl1;
                split_tf32(Kt[(ks*8 + qid    )*68 + col + grp], bh0, bl0);
                split_tf32(Kt[(ks*8 + qid + 4)*68 + col + grp], bh1, bl1);
                mma3(acc_s[jn], ah, al, bh0, bh1, bl0, bl1);
            }
        }
        const bool diag = (j == qt);
        #pragma unroll
        for (int jn = 0; jn < 4; jn++) {
            int c0 = wn*32 + jn*8 + qid*2;
            float v0 = acc_s[jn][0] * 0.125f;
            float v1 = acc_s[jn][1] * 0.125f;
            float v2 = acc_s[jn][2] * 0.125f;
            float v3 = acc_s[jn][3] * 0.125f;
            if (diag) {
                if (c0     > r0    ) v0 = -1e30f;
                if (c0 + 1 > r0    ) v1 = -1e30f;
                if (c0     > r0 + 8) v2 = -1e30f;
                if (c0 + 1 > r0 + 8) v3 = -1e30f;
            }
            Ss[(r0    )*68 + c0    ] = v0;
            Ss[(r0    )*68 + c0 + 1] = v1;
            Ss[(r0 + 8)*68 + c0    ] = v2;
            Ss[(r0 + 8)*68 + c0 + 1] = v3;
        }
        __syncthreads();

        // ---- online softmax, one row per thread ----
        if (tid < 64) {
            float mold = m_sh[tid];
            float mx = mold;
            for (int c = 0; c < 64; c++) mx = fmaxf(mx, Ss[tid*68 + c]);
            float corr = __expf(mold - mx);
            float sum = 0.f;
            for (int c = 0; c < 64; c++) {
                float pv = __expf(Ss[tid*68 + c] - mx);
                Ss[tid*68 + c] = pv;
                sum += pv;
            }
            l_sh[tid] = l_sh[tid]*corr + sum;
            m_sh[tid] = mx;
            c_sh[tid] = corr;
        }
        __syncthreads();

        // ---- O = O*corr + P @ V via 3xTF32 MMA (R8-proven pattern) ----
        {
            float cA = c_sh[r0], cB = c_sh[r0 + 8];
            #pragma unroll
            for (int jn = 0; jn < 4; jn++) {
                acc_o[jn][0] *= cA; acc_o[jn][1] *= cA;
                acc_o[jn][2] *= cB; acc_o[jn][3] *= cB;
            }
            #pragma unroll
            for (int ks = 0; ks < 8; ks++) {
                uint32_t ah[4], al[4];
                split_tf32(Ss[(r0    )*68 + ks*8 + qid    ], ah[0], al[0]);
                split_tf32(Ss[(r0 + 8)*68 + ks*8 + qid    ], ah[1], al[1]);
                split_tf32(Ss[(r0    )*68 + ks*8 + qid + 4], ah[2], al[2]);
                split_tf32(Ss[(r0 + 8)*68 + ks*8 + qid + 4], ah[3], al[3]);
                #pragma unroll
                for (int jn = 0; jn < 4; jn++) {
                    int col = wn*32 + jn*8;
                    uint32_t bh0, bl0, bh1, bl1;
                    split_tf32(Vs[(ks*8 + qid    )*68 + col + grp], bh0, bl0);
                    split_tf32(Vs[(ks*8 + qid + 4)*68 + col + grp], bh1, bl1);
                    mma3(acc_o[jn], ah, al, bh0, bh1, bl0, bl1);
                }
            }
        }
    }
    __syncthreads();

    // ---- epilogue: MMA C layout, mean over heads via atomics ----
    {
        float invA = 1.f / (l_sh[r0    ] * (float)H_);
        float invB = 1.f / (l_sh[r0 + 8] * (float)H_);
        float* dst = &g_M[((size_t)b*S_ + qt*64)*E_];
        #pragma unroll
        for (int jn = 0; jn < 4; jn++) {
            int c0 = wn*32 + jn*8 + qid*2;
            atomicAdd(&dst[(size_t)(r0    )*E_ + c0    ], acc_o[jn][0]*invA);
            atomicAdd(&dst[(size_t)(r0    )*E_ + c0 + 1], acc_o[jn][1]*invA);
            atomicAdd(&dst[(size_t)(r0 + 8)*E_ + c0    ], acc_o[jn][2]*invB);
            atomicAdd(&dst[(size_t)(r0 + 8)*E_ + c0 + 1], acc_o[jn][3]*invB);
        }
    }
}

// ---------------------------------------------------------------------------
// Final linear: G = g_M[512,512] @ Wf[512,512]  (scramble is identity; PROVEN)
__global__ void gemm_g_kernel(const float* __restrict__ Wf) {
    __shared__ float As[64*36];
    __shared__ float Bs[32*68];
    const int tid  = threadIdx.x;
    const int lane = tid & 31;
    const int warp = tid >> 5;
    const int wm = warp >> 1, wn = warp & 1;
    const int grp = lane >> 2, qid = lane & 3;
    const int m0 = blockIdx.x * 64, n0 = blockIdx.y * 64;

    float acc[2][4][4] = {};

    for (int k0 = 0; k0 < 512; k0 += 32) {
        #pragma unroll
        for (int t = 0; t < 4; t++) {
            int f = tid + t*128;
            int r = f >> 3, c = (f & 7) * 4;
            *(float4*)&As[r*36 + c] = *(const float4*)&g_M[(size_t)(m0 + r)*512 + k0 + c];
        }
        #pragma unroll
        for (int t = 0; t < 4; t++) {
            int f = tid + t*128;
            int r = f >> 4, c = (f & 15) * 4;
            *(float4*)&Bs[r*68 + c] = *(const float4*)&Wf[(size_t)(k0 + r)*512 + n0 + c];
        }
        __syncthreads();

        #pragma unroll
        for (int ks = 0; ks < 4; ks++) {
            uint32_t ah[2][4], al[2][4];
            #pragma unroll
            for (int i = 0; i < 2; i++) {
                int row = wm*32 + i*16;
                split_tf32(As[(row+grp  )*36 + ks*8 + qid    ], ah[i][0], al[i][0]);
                split_tf32(As[(row+grp+8)*36 + ks*8 + qid    ], ah[i][1], al[i][1]);
                split_tf32(As[(row+grp  )*36 + ks*8 + qid + 4], ah[i][2], al[i][2]);
                split_tf32(As[(row+grp+8)*36 + ks*8 + qid + 4], ah[i][3], al[i][3]);
            }
            #pragma unroll
            for (int jn = 0; jn < 4; jn++) {
                int col = wn*32 + jn*8;
                uint32_t bh0, bl0, bh1, bl1;
                split_tf32(Bs[(ks*8 + qid    )*68 + col + grp], bh0, bl0);
                split_tf32(Bs[(ks*8 + qid + 4)*68 + col + grp], bh1, bl1);
                mma3(acc[0][jn], ah[0], al[0], bh0, bh1, bl0, bl1);
                mma3(acc[1][jn], ah[1], al[1], bh0, bh1, bl0, bl1);
            }
        }
        __syncthreads();
    }

    #pragma unroll
    for (int i = 0; i < 2; i++) {
        int row0 = m0 + wm*32 + i*16 + grp;
        #pragma unroll
        for (int jn = 0; jn < 4; jn++) {
            int col0 = n0 + wn*32 + jn*8 + qid*2;
            g_G[(size_t)row0*512     + col0    ] = acc[i][jn][0];
            g_G[(size_t)row0*512     + col0 + 1] = acc[i][jn][1];
            g_G[(size_t)(row0+8)*512 + col0    ] = acc[i][jn][2];
            g_G[(size_t)(row0+8)*512 + col0 + 1] = acc[i][jn][3];
        }
    }
}

// ---------------------------------------------------------------------------
__global__ void ln_kernel(const float* __restrict__ query, const float* __restrict__ bf,
                          const float* __restrict__ lnw, const float* __restrict__ lnb,
                          float* __restrict__ out) {
    const int row  = blockIdx.x;
    const int bb   = row >> 10;
    const int r128 = row & 127;
    const float* g    = g_G + ((size_t)bb*128 + r128)*D_;
    const float* qrow = query + (size_t)row*D_;
    const int tid = threadIdx.x;
    float x[4];
    float sum = 0.f;
    #pragma unroll
    for (int t = 0; t < 4; t++) {
        int c = tid + t*128;
        x[t] = g[c] + bf[c] + qrow[c];
        sum += x[t];
    }
    __shared__ float red[4];
    __shared__ float red2[4];
    #pragma unroll
    for (int off = 16; off; off >>= 1) sum += __shfl_xor_sync(0xffffffffu, sum, off);
    if ((tid & 31) == 0) red[tid >> 5] = sum;
    __syncthreads();
    float mean = (red[0]+red[1]+red[2]+red[3]) * (1.f/512.f);

    float sq = 0.f;
    #pragma unroll
    for (int t = 0; t < 4; t++) { float d = x[t] - mean; sq += d*d; }
    #pragma unroll
    for (int off = 16; off; off >>= 1) sq += __shfl_xor_sync(0xffffffffu, sq, off);
    if ((tid & 31) == 0) red2[tid >> 5] = sq;
    __syncthreads();
    float var_num = red2[0]+red2[1]+red2[2]+red2[3];
    float stdv = sqrtf(var_num * (1.f/511.f));
    float inv  = 1.f / (stdv + 1e-6f);
    #pragma unroll
    for (int t = 0; t < 4; t++) {
        int c = tid + t*128;
        out[(size_t)row*D_ + c] = lnw[c]*(x[t]-mean)*inv + lnb[c];
    }
}

// ---------------------------------------------------------------------------
extern "C" void kernel_launch(void* const* d_in, const int* in_sizes, int n_in,
                              void* d_out, int out_size) {
    const float* query = (const float*)d_in[0];
    const float* key   = (const float*)d_in[1];
    const float* value = (const float*)d_in[2];
    // d_in[3] = mask (tril, handled analytically)
    const float* Wq = (const float*)d_in[4];
    const float* bq = (const float*)d_in[5];
    const float* Wk = (const float*)d_in[6];
    const float* bk = (const float*)d_in[7];
    const float* Wv = (const float*)d_in[8];
    const float* bv = (const float*)d_in[9];
    const float* Wf = (const float*)d_in[10];
    const float* bf = (const float*)d_in[11];
    const float* lnw = (const float*)d_in[12];
    const float* lnb = (const float*)d_in[13];
    float* out = (float*)d_out;

    // attn smem: 4 tiles of 64*68 + 3*64 floats = (17408 + 192)*4 = 70400 B
    const size_t attn_smem = (size_t)(4*64*68 + 3*64) * sizeof(float);
    cudaFuncSetAttribute(attn_kernel, cudaFuncAttributeMaxDynamicSharedMemorySize,
                         (int)attn_smem);

    zero_m_kernel<<<64, 256>>>();
    proj_mma_kernel<<<dim3(BS_/64, 17), 128>>>(query, key, value, Wq, bq, Wk, bk, Wv, bv);
    attn_kernel<<<dim3(S_/64, B_, H_), 256, attn_smem>>>();
    gemm_g_kernel<<<dim3(8, 8), 128>>>(Wf);
    ln_kernel<<<BS_, 128>>>(query, bf, lnw, lnb, out);
}

// round 10
// speedup vs baseline: 1.2940x; 1.1348x over previous
#include <cuda_runtime.h>
#include <math.h>
#include <stdint.h>

#define B_ 4
#define S_ 1024
#define D_ 512
#define H_ 8
#define E_ 64
#define BS_ (B_*S_)

// Scratch (device globals — no runtime allocation allowed)
__device__ float g_Q[H_*BS_*E_];     // [H][B*S][E]
__device__ float g_K[H_*BS_*E_];
__device__ float g_V[BS_*E_];
__device__ float g_M[BS_*E_];        // mean-over-heads accumulator
__device__ float g_G[B_*128*D_];     // final-GEMM output [512][512]

// ---------------------------------------------------------------------------
__device__ __forceinline__ uint32_t f2tf32(float x) {
    uint32_t r;
    asm("cvt.rna.tf32.f32 %0, %1;" : "=r"(r) : "f"(x));
    return r;
}
__device__ __forceinline__ void split_tf32(float x, uint32_t& hi, uint32_t& lo) {
    hi = f2tf32(x);
    lo = f2tf32(x - __uint_as_float(hi));
}

// D += A(16x8,row) * B(8x8,col)   tf32, fp32 accum
__device__ __forceinline__ void mma_tf32(float c[4],
                                         uint32_t a0, uint32_t a1, uint32_t a2, uint32_t a3,
                                         uint32_t b0, uint32_t b1) {
    asm volatile(
        "mma.sync.aligned.m16n8k8.row.col.f32.tf32.tf32.f32 "
        "{%0,%1,%2,%3}, {%4,%5,%6,%7}, {%8,%9}, {%0,%1,%2,%3};\n"
        : "+f"(c[0]), "+f"(c[1]), "+f"(c[2]), "+f"(c[3])
        : "r"(a0), "r"(a1), "r"(a2), "r"(a3), "r"(b0), "r"(b1));
}

// 3xTF32: acc += lo*hi + hi*lo + hi*hi  (~fp32 product precision)
__device__ __forceinline__ void mma3(float c[4],
                                     const uint32_t ah[4], const uint32_t al[4],
                                     uint32_t bh0, uint32_t bh1,
                                     uint32_t bl0, uint32_t bl1) {
    mma_tf32(c, al[0], al[1], al[2], al[3], bh0, bh1);
    mma_tf32(c, ah[0], ah[1], ah[2], ah[3], bl0, bl1);
    mma_tf32(c, ah[0], ah[1], ah[2], ah[3], bh0, bh1);
}

// ---------------------------------------------------------------------------
__global__ void zero_m_kernel() {
    int i = blockIdx.x * blockDim.x + threadIdx.x;
    int stride = gridDim.x * blockDim.x;
    for (; i < BS_*E_; i += stride) g_M[i] = 0.f;
}

// ---------------------------------------------------------------------------
// Batched projections via 3xTF32 MMA (PROVEN). p<8: Q head p; p<16: K; 16: V.
__global__ void proj_mma_kernel(const float* __restrict__ q, const float* __restrict__ k,
                                const float* __restrict__ v,
                                const float* __restrict__ Wq, const float* __restrict__ bq,
                                const float* __restrict__ Wk, const float* __restrict__ bk,
                                const float* __restrict__ Wv, const float* __restrict__ bv) {
    const int p = blockIdx.y;
    const float* A; const float* W; const float* bias; float* out;
    if (p < 8)       { A = q; W = Wq + (size_t)p*D_*E_;     bias = bq + p*E_;     out = g_Q + (size_t)p*BS_*E_; }
    else if (p < 16) { A = k; W = Wk + (size_t)(p-8)*D_*E_; bias = bk + (p-8)*E_; out = g_K + (size_t)(p-8)*BS_*E_; }
    else             { A = v; W = Wv;                        bias = bv;            out = g_V; }

    __shared__ float As[64*36];   // [row][k]  64x32 chunk, stride 36 OK (32<36)
    __shared__ float Bs[32*68];   // [k][n]    stride 68

    const int tid  = threadIdx.x;
    const int lane = tid & 31;
    const int warp = tid >> 5;
    const int wm = warp >> 1, wn = warp & 1;
    const int grp = lane >> 2, qid = lane & 3;
    const int m0 = blockIdx.x * 64;

    float acc[2][4][4] = {};

    for (int k0 = 0; k0 < D_; k0 += 32) {
        #pragma unroll
        for (int t = 0; t < 4; t++) {
            int f = tid + t*128;
            int r = f >> 3, c = (f & 7) * 4;
            *(float4*)&As[r*36 + c] = *(const float4*)&A[(size_t)(m0 + r)*D_ + k0 + c];
        }
        #pragma unroll
        for (int t = 0; t < 4; t++) {
            int f = tid + t*128;
            int r = f >> 4, c = (f & 15) * 4;
            *(float4*)&Bs[r*68 + c] = *(const float4*)&W[(size_t)(k0 + r)*E_ + c];
        }
        __syncthreads();

        #pragma unroll
        for (int ks = 0; ks < 4; ks++) {
            uint32_t ah[2][4], al[2][4];
            #pragma unroll
            for (int i = 0; i < 2; i++) {
                int row = wm*32 + i*16;
                split_tf32(As[(row+grp  )*36 + ks*8 + qid    ], ah[i][0], al[i][0]);
                split_tf32(As[(row+grp+8)*36 + ks*8 + qid    ], ah[i][1], al[i][1]);
                split_tf32(As[(row+grp  )*36 + ks*8 + qid + 4], ah[i][2], al[i][2]);
                split_tf32(As[(row+grp+8)*36 + ks*8 + qid + 4], ah[i][3], al[i][3]);
            }
            #pragma unroll
            for (int j = 0; j < 4; j++) {
                int col = wn*32 + j*8;
                uint32_t bh0, bl0, bh1, bl1;
                split_tf32(Bs[(ks*8 + qid    )*68 + col + grp], bh0, bl0);
                split_tf32(Bs[(ks*8 + qid + 4)*68 + col + grp], bh1, bl1);
                mma3(acc[0][j], ah[0], al[0], bh0, bh1, bl0, bl1);
                mma3(acc[1][j], ah[1], al[1], bh0, bh1, bl0, bl1);
            }
        }
        __syncthreads();
    }

    #pragma unroll
    for (int i = 0; i < 2; i++) {
        int row0 = m0 + wm*32 + i*16 + grp;
        #pragma unroll
        for (int j = 0; j < 4; j++) {
            int col0 = wn*32 + j*8 + qid*2;
            out[(size_t)row0*E_     + col0    ] = acc[i][j][0] + bias[col0    ];
            out[(size_t)row0*E_     + col0 + 1] = acc[i][j][1] + bias[col0 + 1];
            out[(size_t)(row0+8)*E_ + col0    ] = acc[i][j][2] + bias[col0    ];
            out[(size_t)(row0+8)*E_ + col0 + 1] = acc[i][j][3] + bias[col0 + 1];
        }
    }
}

// ---------------------------------------------------------------------------
// Full-MMA flash attention, round 10:
//  - QK^T: 3xTF32 (score precision matters through softmax)
//  - PV:   single-pass TF32 (P in [0,1], V; ~2^-11 relative on the attention
//          output which is ~10% of LN input -> ~8e-5 final, inside budget).
//          P stored as tf32 BITS by softmax; V converted to tf32 at load.
//  - softmax: 4 threads per row (all 8 warps active), shfl combine.
// 256 threads, 8 warps: warp tile rows wm*16 (+8), cols wn*32.
__global__ void attn_kernel() {
    const int qt = blockIdx.x, b = blockIdx.y, h = blockIdx.z;
    extern __shared__ float sm[];
    float*    Qs  = sm;                    // 64*68 [q][e] fp32
    float*    Kt  = Qs + 64*68;            // 64*68 [e][key] fp32
    uint32_t* VsU = (uint32_t*)(Kt + 64*68); // 64*68 [key][e] tf32 bits
    float*    Ss  = (float*)(VsU + 64*68);   // 64*68 scores fp32 -> P tf32 bits
    uint32_t* SsU = (uint32_t*)Ss;
    float* m_sh = Ss + 64*68;
    float* l_sh = m_sh + 64;
    float* c_sh = l_sh + 64;

    const int tid  = threadIdx.x;
    const int lane = tid & 31;
    const int warp = tid >> 5;                   // 0..7
    const int wm = warp >> 1, wn = warp & 1;
    const int grp = lane >> 2, qid = lane & 3;
    const int r0 = wm*16 + grp;                  // this thread's C rows: r0, r0+8

    const float* Qp = g_Q + (((size_t)h*B_ + b)*S_ + (size_t)qt*64)*E_;
    const float* Kp = g_K + ((size_t)h*B_ + b)*S_*E_;
    const float* Vp = g_V + (size_t)b*S_*E_;

    #pragma unroll
    for (int t = 0; t < 4; t++) {
        int f = tid + t*256;
        int r = f >> 4, c = (f & 15) * 4;
        *(float4*)&Qs[r*68 + c] = *(const float4*)&Qp[(size_t)r*64 + c];
    }
    if (tid < 64) { m_sh[tid] = -1e30f; l_sh[tid] = 0.f; }

    float acc_o[4][4] = {};                      // PV accumulator (C layout)

    for (int j = 0; j <= qt; j++) {
        __syncthreads();   // prev PV reads done; Qs/init visible on iter 0
        #pragma unroll
        for (int t = 0; t < 4; t++) {
            int f = tid + t*256;
            int r = f >> 4, c = (f & 15) * 4;   // r = key row, c = e base
            float4 kv = *(const float4*)&Kp[(size_t)(j*64 + r)*64 + c];
            Kt[(c+0)*68 + r] = kv.x;            // transpose: [e][key]
            Kt[(c+1)*68 + r] = kv.y;
            Kt[(c+2)*68 + r] = kv.z;
            Kt[(c+3)*68 + r] = kv.w;
            float4 vv = *(const float4*)&Vp[(size_t)(j*64 + r)*64 + c];
            VsU[r*68 + c + 0] = f2tf32(vv.x);   // tf32 bits for 1x PV
            VsU[r*68 + c + 1] = f2tf32(vv.y);
            VsU[r*68 + c + 2] = f2tf32(vv.z);
            VsU[r*68 + c + 3] = f2tf32(vv.w);
        }
        __syncthreads();

        // ---- S = Q @ K^T via 3xTF32 MMA ----
        float acc_s[4][4] = {};
        #pragma unroll
        for (int ks = 0; ks < 8; ks++) {
            uint32_t ah[4], al[4];
            split_tf32(Qs[(r0    )*68 + ks*8 + qid    ], ah[0], al[0]);
            split_tf32(Qs[(r0 + 8)*68 + ks*8 + qid    ], ah[1], al[1]);
            split_tf32(Qs[(r0    )*68 + ks*8 + qid + 4], ah[2], al[2]);
            split_tf32(Qs[(r0 + 8)*68 + ks*8 + qid + 4], ah[3], al[3]);
            #pragma unroll
            for (int jn = 0; jn < 4; jn++) {
                int col = wn*32 + jn*8;
                uint32_t bh0, bl0, bh1, bl1;
                split_tf32(Kt[(ks*8 + qid    )*68 + col + grp], bh0, bl0);
                split_tf32(Kt[(ks*8 + qid + 4)*68 + col + grp], bh1, bl1);
                mma3(acc_s[jn], ah, al, bh0, bh1, bl0, bl1);
            }
        }
        const bool diag = (j == qt);
        #pragma unroll
        for (int jn = 0; jn < 4; jn++) {
            int c0 = wn*32 + jn*8 + qid*2;
            float v0 = acc_s[jn][0] * 0.125f;
            float v1 = acc_s[jn][1] * 0.125f;
            float v2 = acc_s[jn][2] * 0.125f;
            float v3 = acc_s[jn][3] * 0.125f;
            if (diag) {
                if (c0     > r0    ) v0 = -1e30f;
                if (c0 + 1 > r0    ) v1 = -1e30f;
                if (c0     > r0 + 8) v2 = -1e30f;
                if (c0 + 1 > r0 + 8) v3 = -1e30f;
            }
            Ss[(r0    )*68 + c0    ] = v0;
            Ss[(r0    )*68 + c0 + 1] = v1;
            Ss[(r0 + 8)*68 + c0    ] = v2;
            Ss[(r0 + 8)*68 + c0 + 1] = v3;
        }
        __syncthreads();

        // ---- online softmax: 4 threads/row, shfl combine; P -> tf32 bits ----
        {
            const int row  = tid >> 2;
            const int part = tid & 3;
            const int base = row*68 + part*16;
            float mold = m_sh[row];
            float mx = -1e30f;
            #pragma unroll
            for (int c = 0; c < 16; c++) mx = fmaxf(mx, Ss[base + c]);
            mx = fmaxf(mx, __shfl_xor_sync(0xffffffffu, mx, 1));
            mx = fmaxf(mx, __shfl_xor_sync(0xffffffffu, mx, 2));
            mx = fmaxf(mx, mold);
            float sum = 0.f;
            #pragma unroll
            for (int c = 0; c < 16; c++) {
                float pv = __expf(Ss[base + c] - mx);
                sum += pv;
                SsU[base + c] = f2tf32(pv);
            }
            sum += __shfl_xor_sync(0xffffffffu, sum, 1);
            sum += __shfl_xor_sync(0xffffffffu, sum, 2);
            if (part == 0) {
                float corr = __expf(mold - mx);
                l_sh[row] = l_sh[row]*corr + sum;
                m_sh[row] = mx;
                c_sh[row] = corr;
            }
        }
        __syncthreads();

        // ---- O = O*corr + P @ V via single-pass TF32 MMA ----
        {
            float cA = c_sh[r0], cB = c_sh[r0 + 8];
            #pragma unroll
            for (int jn = 0; jn < 4; jn++) {
                acc_o[jn][0] *= cA; acc_o[jn][1] *= cA;
                acc_o[jn][2] *= cB; acc_o[jn][3] *= cB;
            }
            #pragma unroll
            for (int ks = 0; ks < 8; ks++) {
                uint32_t a0 = SsU[(r0    )*68 + ks*8 + qid    ];
                uint32_t a1 = SsU[(r0 + 8)*68 + ks*8 + qid    ];
                uint32_t a2 = SsU[(r0    )*68 + ks*8 + qid + 4];
                uint32_t a3 = SsU[(r0 + 8)*68 + ks*8 + qid + 4];
                #pragma unroll
                for (int jn = 0; jn < 4; jn++) {
                    int col = wn*32 + jn*8;
                    uint32_t b0 = VsU[(ks*8 + qid    )*68 + col + grp];
                    uint32_t b1 = VsU[(ks*8 + qid + 4)*68 + col + grp];
                    mma_tf32(acc_o[jn], a0, a1, a2, a3, b0, b1);
                }
            }
        }
    }
    __syncthreads();

    // ---- epilogue: MMA C layout, mean over heads via atomics ----
    {
        float invA = 1.f / (l_sh[r0    ] * (float)H_);
        float invB = 1.f / (l_sh[r0 + 8] * (float)H_);
        float* dst = &g_M[((size_t)b*S_ + qt*64)*E_];
        #pragma unroll
        for (int jn = 0; jn < 4; jn++) {
            int c0 = wn*32 + jn*8 + qid*2;
            atomicAdd(&dst[(size_t)(r0    )*E_ + c0    ], acc_o[jn][0]*invA);
            atomicAdd(&dst[(size_t)(r0    )*E_ + c0 + 1], acc_o[jn][1]*invA);
            atomicAdd(&dst[(size_t)(r0 + 8)*E_ + c0    ], acc_o[jn][2]*invB);
            atomicAdd(&dst[(size_t)(r0 + 8)*E_ + c0 + 1], acc_o[jn][3]*invB);
        }
    }
}

// ---------------------------------------------------------------------------
// Final linear: G = g_M[512,512] @ Wf[512,512]  (scramble is identity; PROVEN)
__global__ void gemm_g_kernel(const float* __restrict__ Wf) {
    __shared__ float As[64*36];
    __shared__ float Bs[32*68];
    const int tid  = threadIdx.x;
    const int lane = tid & 31;
    const int warp = tid >> 5;
    const int wm = warp >> 1, wn = warp & 1;
    const int grp = lane >> 2, qid = lane & 3;
    const int m0 = blockIdx.x * 64, n0 = blockIdx.y * 64;

    float acc[2][4][4] = {};

    for (int k0 = 0; k0 < 512; k0 += 32) {
        #pragma unroll
        for (int t = 0; t < 4; t++) {
            int f = tid + t*128;
            int r = f >> 3, c = (f & 7) * 4;
            *(float4*)&As[r*36 + c] = *(const float4*)&g_M[(size_t)(m0 + r)*512 + k0 + c];
        }
        #pragma unroll
        for (int t = 0; t < 4; t++) {
            int f = tid + t*128;
            int r = f >> 4, c = (f & 15) * 4;
            *(float4*)&Bs[r*68 + c] = *(const float4*)&Wf[(size_t)(k0 + r)*512 + n0 + c];
        }
        __syncthreads();

        #pragma unroll
        for (int ks = 0; ks < 4; ks++) {
            uint32_t ah[2][4], al[2][4];
            #pragma unroll
            for (int i = 0; i < 2; i++) {
                int row = wm*32 + i*16;
                split_tf32(As[(row+grp  )*36 + ks*8 + qid    ], ah[i][0], al[i][0]);
                split_tf32(As[(row+grp+8)*36 + ks*8 + qid    ], ah[i][1], al[i][1]);
                split_tf32(As[(row+grp  )*36 + ks*8 + qid + 4], ah[i][2], al[i][2]);
                split_tf32(As[(row+grp+8)*36 + ks*8 + qid + 4], ah[i][3], al[i][3]);
            }
            #pragma unroll
            for (int jn = 0; jn < 4; jn++) {
                int col = wn*32 + jn*8;
                uint32_t bh0, bl0, bh1, bl1;
                split_tf32(Bs[(ks*8 + qid    )*68 + col + grp], bh0, bl0);
                split_tf32(Bs[(ks*8 + qid + 4)*68 + col + grp], bh1, bl1);
                mma3(acc[0][jn], ah[0], al[0], bh0, bh1, bl0, bl1);
                mma3(acc[1][jn], ah[1], al[1], bh0, bh1, bl0, bl1);
            }
        }
        __syncthreads();
    }

    #pragma unroll
    for (int i = 0; i < 2; i++) {
        int row0 = m0 + wm*32 + i*16 + grp;
        #pragma unroll
        for (int jn = 0; jn < 4; jn++) {
            int col0 = n0 + wn*32 + jn*8 + qid*2;
            g_G[(size_t)row0*512     + col0    ] = acc[i][jn][0];
            g_G[(size_t)row0*512     + col0 + 1] = acc[i][jn][1];
            g_G[(size_t)(row0+8)*512 + col0    ] = acc[i][jn][2];
            g_G[(size_t)(row0+8)*512 + col0 + 1] = acc[i][jn][3];
        }
    }
}

// ---------------------------------------------------------------------------
__global__ void ln_kernel(const float* __restrict__ query, const float* __restrict__ bf,
                          const float* __restrict__ lnw, const float* __restrict__ lnb,
                          float* __restrict__ out) {
    const int row  = blockIdx.x;
    const int bb   = row >> 10;
    const int r128 = row & 127;
    const float* g    = g_G + ((size_t)bb*128 + r128)*D_;
    const float* qrow = query + (size_t)row*D_;
    const int tid = threadIdx.x;
    float x[4];
    float sum = 0.f;
    #pragma unroll
    for (int t = 0; t < 4; t++) {
        int c = tid + t*128;
        x[t] = g[c] + bf[c] + qrow[c];
        sum += x[t];
    }
    __shared__ float red[4];
    __shared__ float red2[4];
    #pragma unroll
    for (int off = 16; off; off >>= 1) sum += __shfl_xor_sync(0xffffffffu, sum, off);
    if ((tid & 31) == 0) red[tid >> 5] = sum;
    __syncthreads();
    float mean = (red[0]+red[1]+red[2]+red[3]) * (1.f/512.f);

    float sq = 0.f;
    #pragma unroll
    for (int t = 0; t < 4; t++) { float d = x[t] - mean; sq += d*d; }
    #pragma unroll
    for (int off = 16; off; off >>= 1) sq += __shfl_xor_sync(0xffffffffu, sq, off);
    if ((tid & 31) == 0) red2[tid >> 5] = sq;
    __syncthreads();
    float var_num = red2[0]+red2[1]+red2[2]+red2[3];
    float stdv = sqrtf(var_num * (1.f/511.f));
    float inv  = 1.f / (stdv + 1e-6f);
    #pragma unroll
    for (int t = 0; t < 4; t++) {
        int c = tid + t*128;
        out[(size_t)row*D_ + c] = lnw[c]*(x[t]-mean)*inv + lnb[c];
    }
}

// ---------------------------------------------------------------------------
extern "C" void kernel_launch(void* const* d_in, const int* in_sizes, int n_in,
                              void* d_out, int out_size) {
    const float* query = (const float*)d_in[0];
    const float* key   = (const float*)d_in[1];
    const float* value = (const float*)d_in[2];
    // d_in[3] = mask (tril, handled analytically)
    const float* Wq = (const float*)d_in[4];
    const float* bq = (const float*)d_in[5];
    const float* Wk = (const float*)d_in[6];
    const float* bk = (const float*)d_in[7];
    const float* Wv = (const float*)d_in[8];
    const float* bv = (const float*)d_in[9];
    const float* Wf = (const float*)d_in[10];
    const float* bf = (const float*)d_in[11];
    const float* lnw = (const float*)d_in[12];
    const float* lnb = (const float*)d_in[13];
    float* out = (float*)d_out;

    // attn smem: 4 tiles of 64*68 + 3*64 floats = 70400 B
    const size_t attn_smem = (size_t)(4*64*68 + 3*64) * sizeof(float);
    cudaFuncSetAttribute(attn_kernel, cudaFuncAttributeMaxDynamicSharedMemorySize,
                         (int)attn_smem);

    zero_m_kernel<<<64, 256>>>();
    proj_mma_kernel<<<dim3(BS_/64, 17), 128>>>(query, key, value, Wq, bq, Wk, bk, Wv, bv);
    attn_kernel<<<dim3(S_/64, B_, H_), 256, attn_smem>>>();
    gemm_g_kernel<<<dim3(8, 8), 128>>>(Wf);
    ln_kernel<<<BS_, 128>>>(query, bf, lnw, lnb, out);
}